// round 5
// baseline (speedup 1.0000x reference)
#include <cuda_runtime.h>
#include <cstdint>

#define NBLK  592        // 148 SMs x 4 blocks/SM -> exactly one wave
#define TPB   256
#define WPB   8          // warps per block
#define NBINS 15
#define NCOL  45         // 15 counts, 15 conf sums, 15 acc sums
#define PAD   16         // spread accumulators across L2 lines (16 doubles = 128B)

// Global double accumulators + completion ticket. Zero-initialized at module
// load; the finishing block re-zeroes them so every graph replay starts clean.
__device__ double g_red[NCOL * PAD];
__device__ unsigned int g_ticket;

__device__ __forceinline__ float ex2f(float x) {
    float r; asm("ex2.approx.f32 %0, %1;" : "=f"(r) : "f"(x)); return r;
}

// Final ECE from the 15 bins, executed by the last-arriving block.
// Reads g_red, writes out[0], then re-zeroes g_red and the ticket.
__device__ __forceinline__ void finalize_ece(float* out, double n, int tid)
{
    __threadfence();   // make all blocks' atomics visible to this block
    double e = 0.0;
    if (tid < 32) {
        if (tid < NBINS) {
            const double c  = g_red[tid * PAD];
            const double cs = g_red[(NBINS + tid) * PAD];
            const double as = g_red[(2 * NBINS + tid) * PAD];
            if (c > 0.0) {
                const double d = (c > 1.0) ? c : 1.0;
                e = fabs(cs / d - as / d) * (c / n);
            }
        }
#pragma unroll
        for (int o = 16; o > 0; o >>= 1)
            e += __shfl_xor_sync(0xffffffffu, e, o);
    }
    __syncthreads();                       // reads of g_red complete
    for (int i = tid; i < NCOL * PAD; i += TPB)
        g_red[i] = 0.0;                    // clean slate for next replay
    if (tid == 0) {
        g_ticket = 0;
        out[0] = (float)e;
    }
}

// ---------------------------------------------------------------------------
// Main pass, specialized C=100, fused finalization. Layout: 4 lanes per row,
// 8 rows per warp. Lane (grp, q) loads float4 indices q,q+4,...,q+20 (96
// elems) plus scalar 96+q -> 25 floats/lane, row register-resident.
// acc via logits[row,label] == rowmax.
// ---------------------------------------------------------------------------
__global__ __launch_bounds__(TPB, 4)
void ece_pass1_c100(const float* __restrict__ logits,
                    const int*   __restrict__ labels,
                    int N, float* __restrict__ out, double nAll)
{
    const int tid  = threadIdx.x;
    const int lane = tid & 31;
    const int q    = lane & 3;          // sub-lane within row group
    const int grp  = lane >> 2;         // row group within warp (0..7)
    const int warpId = blockIdx.x * WPB + (tid >> 5);
    const int rowStride = NBLK * WPB * 8;   // rows per sweep

    const float L2E = 1.4426950408889634f;

    // Register histogram: lane q owns bins {q, q+4, q+8, q+12}
    float cnt[4]  = {0.f, 0.f, 0.f, 0.f};
    float csum[4] = {0.f, 0.f, 0.f, 0.f};
    float asum[4] = {0.f, 0.f, 0.f, 0.f};

    // Prefetch first label
    int base0 = warpId * 8;
    int lab_next = 0;
    if (base0 < N) {
        int r0 = base0 + grp;
        lab_next = labels[(r0 < N) ? r0 : (N - 1)];
    }

#pragma unroll 1
    for (int base = base0; base < N; base += rowStride) {
        const int  row   = base + grp;
        const bool valid = (row < N);
        const int  rowl  = valid ? row : (N - 1);

        const float* rp   = logits + (size_t)rowl * 100;
        const float4* rp4 = reinterpret_cast<const float4*>(rp);

        const int   lab    = lab_next;
        const float labval = rp[lab];

        float4 a0 = rp4[q];
        float4 a1 = rp4[q + 4];
        float4 a2 = rp4[q + 8];
        float4 a3 = rp4[q + 12];
        float4 a4 = rp4[q + 16];
        float4 a5 = rp4[q + 20];
        float  tl = rp[96 + q];

        // Prefetch next iteration's label (independent stream)
        {
            const int nb = base + rowStride;
            if (nb < N) {
                int nr = nb + grp;
                lab_next = labels[(nr < N) ? nr : (N - 1)];
            }
        }

        // ---- row max ----
        float m0 = fmaxf(fmaxf(a0.x, a0.y), fmaxf(a0.z, a0.w));
        float m1 = fmaxf(fmaxf(a1.x, a1.y), fmaxf(a1.z, a1.w));
        float m2 = fmaxf(fmaxf(a2.x, a2.y), fmaxf(a2.z, a2.w));
        float m3 = fmaxf(fmaxf(a3.x, a3.y), fmaxf(a3.z, a3.w));
        float m4 = fmaxf(fmaxf(a4.x, a4.y), fmaxf(a4.z, a4.w));
        float m5 = fmaxf(fmaxf(a5.x, a5.y), fmaxf(a5.z, a5.w));
        float m  = fmaxf(fmaxf(fmaxf(m0, m1), fmaxf(m2, m3)),
                         fmaxf(fmaxf(m4, m5), tl));
        m = fmaxf(m, __shfl_xor_sync(0xffffffffu, m, 1));
        m = fmaxf(m, __shfl_xor_sync(0xffffffffu, m, 2));

        // ---- sum exp(v - m) ----
        const float mb = m * L2E;
#define E(v) ex2f(fmaf((v), L2E, -mb))
        float s0 = (E(a0.x) + E(a0.y)) + (E(a0.z) + E(a0.w));
        float s1 = (E(a1.x) + E(a1.y)) + (E(a1.z) + E(a1.w));
        float s2 = (E(a2.x) + E(a2.y)) + (E(a2.z) + E(a2.w));
        float s3 = (E(a3.x) + E(a3.y)) + (E(a3.z) + E(a3.w));
        float s4 = (E(a4.x) + E(a4.y)) + (E(a4.z) + E(a4.w));
        float s5 = (E(a5.x) + E(a5.y)) + (E(a5.z) + E(a5.w));
        float s  = ((s0 + s1) + (s2 + s3)) + ((s4 + s5) + E(tl));
#undef E
        s += __shfl_xor_sync(0xffffffffu, s, 1);
        s += __shfl_xor_sync(0xffffffffu, s, 2);

        const float conf = 1.0f / s;                 // = max softmax prob
        const float accv = (labval == m) ? 1.0f : 0.0f;
        int bin = (int)(conf * 15.0f);
        bin = min(bin, NBINS - 1);

        const bool mine = valid && ((bin & 3) == q);
        const int  slot = bin >> 2;
#pragma unroll
        for (int ss = 0; ss < 4; ss++) {
            if (mine && slot == ss) {
                cnt[ss]  += 1.0f;
                csum[ss] += conf;
                asum[ss] += accv;
            }
        }
    }

    // ---- combine the 8 groups within the warp (xor 4, 8, 16) ----
#pragma unroll
    for (int ss = 0; ss < 4; ss++) {
#pragma unroll
        for (int d = 4; d < 32; d <<= 1) {
            cnt[ss]  += __shfl_xor_sync(0xffffffffu, cnt[ss],  d);
            csum[ss] += __shfl_xor_sync(0xffffffffu, csum[ss], d);
            asum[ss] += __shfl_xor_sync(0xffffffffu, asum[ss], d);
        }
    }

    // ---- combine warps within the block, then one atomic round per block ----
    __shared__ float sh[NCOL];
    __shared__ bool  sLast;
    if (tid < NCOL) sh[tid] = 0.0f;
    __syncthreads();
    if (lane < 4) {
#pragma unroll
        for (int ss = 0; ss < 4; ss++) {
            const int bin = q + 4 * ss;
            if (bin < NBINS) {
                atomicAdd(&sh[bin],             cnt[ss]);
                atomicAdd(&sh[NBINS + bin],     csum[ss]);
                atomicAdd(&sh[2 * NBINS + bin], asum[ss]);
            }
        }
    }
    __syncthreads();
    if (tid < NCOL)
        atomicAdd(&g_red[tid * PAD], (double)sh[tid]);

    // ---- last block finalizes ----
    __threadfence();
    if (tid == 0)
        sLast = (atomicAdd(&g_ticket, 1u) == (unsigned)(gridDim.x - 1));
    __syncthreads();
    if (sLast)
        finalize_ece(out, nAll, tid);
}

// ---------------------------------------------------------------------------
// Generic fallback (any C): warp per row, fused finalization.
// ---------------------------------------------------------------------------
__global__ __launch_bounds__(TPB)
void ece_pass1_generic(const float* __restrict__ logits,
                       const int*   __restrict__ labels,
                       int N, int C, float* __restrict__ out, double nAll)
{
    const int tid  = threadIdx.x;
    const int lane = tid & 31;
    const int warpId = blockIdx.x * WPB + (tid >> 5);
    const int nWarps = NBLK * WPB;
    const float L2E = 1.4426950408889634f;

    __shared__ float sh[NCOL];
    __shared__ bool  sLast;
    if (tid < NCOL) sh[tid] = 0.0f;
    __syncthreads();

    for (int row = warpId; row < N; row += nWarps) {
        const float* rp = logits + (size_t)row * C;
        float m = -3.4e38f;
        int am = 0x7fffffff;
        for (int j = lane; j < C; j += 32) {
            float v = rp[j];
            if (v > m) { m = v; am = j; }
        }
#pragma unroll
        for (int d = 1; d < 32; d <<= 1) {
            float om = __shfl_xor_sync(0xffffffffu, m, d);
            int   oa = __shfl_xor_sync(0xffffffffu, am, d);
            if (om > m || (om == m && oa < am)) { m = om; am = oa; }
        }
        const float mb = m * L2E;
        float s = 0.f;
        for (int j = lane; j < C; j += 32)
            s += ex2f(fmaf(rp[j], L2E, -mb));
#pragma unroll
        for (int d = 1; d < 32; d <<= 1)
            s += __shfl_xor_sync(0xffffffffu, s, d);

        if (lane == 0) {
            const float conf = 1.0f / s;
            const float accv = (am == labels[row]) ? 1.0f : 0.0f;
            int bin = (int)(conf * 15.0f);
            bin = min(bin, NBINS - 1);
            atomicAdd(&sh[bin],             1.0f);
            atomicAdd(&sh[NBINS + bin],     conf);
            atomicAdd(&sh[2 * NBINS + bin], accv);
        }
    }
    __syncthreads();
    if (tid < NCOL)
        atomicAdd(&g_red[tid * PAD], (double)sh[tid]);

    __threadfence();
    if (tid == 0)
        sLast = (atomicAdd(&g_ticket, 1u) == (unsigned)(gridDim.x - 1));
    __syncthreads();
    if (sLast)
        finalize_ece(out, nAll, tid);
}

extern "C" void kernel_launch(void* const* d_in, const int* in_sizes, int n_in,
                              void* d_out, int out_size)
{
    const float* logits = (const float*)d_in[0];
    const int*   labels = (const int*)d_in[1];
    const long long total = (long long)in_sizes[0];
    const int N = in_sizes[1];
    const int C = (int)(total / N);

    if (C == 100)
        ece_pass1_c100<<<NBLK, TPB>>>(logits, labels, N, (float*)d_out, (double)N);
    else
        ece_pass1_generic<<<NBLK, TPB>>>(logits, labels, N, C, (float*)d_out, (double)N);
}

// round 9
// speedup vs baseline: 1.1255x; 1.1255x over previous
#include <cuda_runtime.h>
#include <cstdint>

#define NBLK  592        // 148 SMs x 4 blocks/SM -> exactly one wave
#define TPB   256
#define WPB   8          // warps per block
#define NBINS 15
#define NCOL  45         // 15 counts, 15 conf sums, 15 acc sums
#define PAD   16         // spread accumulators across L2 lines (16 doubles = 128B)

// Global double accumulators + completion ticket. Zero-initialized at module
// load; the finishing block re-zeroes them so every graph replay starts clean.
__device__ double g_red[NCOL * PAD];
__device__ unsigned int g_ticket;

__device__ __forceinline__ float ex2f(float x) {
    float r; asm("ex2.approx.f32 %0, %1;" : "=f"(r) : "f"(x)); return r;
}

// Final ECE from the 15 bins, executed by the last-arriving block.
// __noinline__ so its register/double usage cannot perturb the hot loop.
__device__ __noinline__ void finalize_ece(float* out, double n, int tid)
{
    __threadfence();   // make all blocks' atomics visible to this block
    double e = 0.0;
    if (tid < 32) {
        if (tid < NBINS) {
            const double c  = g_red[tid * PAD];
            const double cs = g_red[(NBINS + tid) * PAD];
            const double as = g_red[(2 * NBINS + tid) * PAD];
            if (c > 0.0) {
                const double d = (c > 1.0) ? c : 1.0;
                e = fabs(cs / d - as / d) * (c / n);
            }
        }
#pragma unroll
        for (int o = 16; o > 0; o >>= 1)
            e += __shfl_xor_sync(0xffffffffu, e, o);
    }
    __syncthreads();                       // reads of g_red complete
    for (int i = tid; i < NCOL * PAD; i += TPB)
        g_red[i] = 0.0;                    // clean slate for next replay
    if (tid == 0) {
        g_ticket = 0;
        out[0] = (float)e;
    }
}

// ---------------------------------------------------------------------------
// Main pass, specialized C=100 (round-3 loop body, unchanged). Layout: 4
// lanes per row, 8 rows per warp. Lane (grp, q) loads float4 indices
// q,q+4,...,q+20 (96 elems) plus scalar 96+q -> 25 floats/lane.
// acc via logits[row,label] == rowmax.
// ---------------------------------------------------------------------------
__global__ __launch_bounds__(TPB, 4)
void ece_pass1_c100(const float* __restrict__ logits,
                    const int*   __restrict__ labels,
                    int N, float* __restrict__ out, double nAll)
{
    const int tid  = threadIdx.x;
    const int lane = tid & 31;
    const int q    = lane & 3;          // sub-lane within row group
    const int grp  = lane >> 2;         // row group within warp (0..7)
    const int warpId = blockIdx.x * WPB + (tid >> 5);
    const int rowStride = NBLK * WPB * 8;   // rows per sweep

    const float L2E = 1.4426950408889634f;

    // Register histogram: lane q owns bins {q, q+4, q+8, q+12}
    float cnt[4]  = {0.f, 0.f, 0.f, 0.f};
    float csum[4] = {0.f, 0.f, 0.f, 0.f};
    float asum[4] = {0.f, 0.f, 0.f, 0.f};

#pragma unroll 1
    for (int base = warpId * 8; base < N; base += rowStride) {
        const int  row   = base + grp;
        const bool valid = (row < N);
        const int  rowl  = valid ? row : (N - 1);

        const float* rp   = logits + (size_t)rowl * 100;
        const float4* rp4 = reinterpret_cast<const float4*>(rp);

        // label + the label's logit (same cache lines as the row loads)
        const int   lab    = labels[rowl];
        const float labval = rp[lab];

        float4 a0 = rp4[q];
        float4 a1 = rp4[q + 4];
        float4 a2 = rp4[q + 8];
        float4 a3 = rp4[q + 12];
        float4 a4 = rp4[q + 16];
        float4 a5 = rp4[q + 20];
        float  tl = rp[96 + q];

        // ---- row max (balanced tree, then 2 shfl levels over the 4 lanes) ----
        float m0 = fmaxf(fmaxf(a0.x, a0.y), fmaxf(a0.z, a0.w));
        float m1 = fmaxf(fmaxf(a1.x, a1.y), fmaxf(a1.z, a1.w));
        float m2 = fmaxf(fmaxf(a2.x, a2.y), fmaxf(a2.z, a2.w));
        float m3 = fmaxf(fmaxf(a3.x, a3.y), fmaxf(a3.z, a3.w));
        float m4 = fmaxf(fmaxf(a4.x, a4.y), fmaxf(a4.z, a4.w));
        float m5 = fmaxf(fmaxf(a5.x, a5.y), fmaxf(a5.z, a5.w));
        float m  = fmaxf(fmaxf(fmaxf(m0, m1), fmaxf(m2, m3)),
                         fmaxf(fmaxf(m4, m5), tl));
        m = fmaxf(m, __shfl_xor_sync(0xffffffffu, m, 1));
        m = fmaxf(m, __shfl_xor_sync(0xffffffffu, m, 2));

        // ---- sum exp(v - m), independent accumulators ----
        const float mb = m * L2E;
#define E(v) ex2f(fmaf((v), L2E, -mb))
        float s0 = (E(a0.x) + E(a0.y)) + (E(a0.z) + E(a0.w));
        float s1 = (E(a1.x) + E(a1.y)) + (E(a1.z) + E(a1.w));
        float s2 = (E(a2.x) + E(a2.y)) + (E(a2.z) + E(a2.w));
        float s3 = (E(a3.x) + E(a3.y)) + (E(a3.z) + E(a3.w));
        float s4 = (E(a4.x) + E(a4.y)) + (E(a4.z) + E(a4.w));
        float s5 = (E(a5.x) + E(a5.y)) + (E(a5.z) + E(a5.w));
        float s  = ((s0 + s1) + (s2 + s3)) + ((s4 + s5) + E(tl));
#undef E
        s += __shfl_xor_sync(0xffffffffu, s, 1);
        s += __shfl_xor_sync(0xffffffffu, s, 2);

        const float conf = 1.0f / s;                 // = max softmax prob
        const float accv = (labval == m) ? 1.0f : 0.0f;
        int bin = (int)(conf * 15.0f);
        bin = min(bin, NBINS - 1);

        const bool mine = valid && ((bin & 3) == q);
        const int  slot = bin >> 2;
#pragma unroll
        for (int ss = 0; ss < 4; ss++) {
            if (mine && slot == ss) {
                cnt[ss]  += 1.0f;
                csum[ss] += conf;
                asum[ss] += accv;
            }
        }
    }

    // ---- combine the 8 groups within the warp (xor 4, 8, 16) ----
#pragma unroll
    for (int ss = 0; ss < 4; ss++) {
#pragma unroll
        for (int d = 4; d < 32; d <<= 1) {
            cnt[ss]  += __shfl_xor_sync(0xffffffffu, cnt[ss],  d);
            csum[ss] += __shfl_xor_sync(0xffffffffu, csum[ss], d);
            asum[ss] += __shfl_xor_sync(0xffffffffu, asum[ss], d);
        }
    }

    // ---- combine warps within the block, then one atomic round per block ----
    __shared__ float sh[NCOL];
    __shared__ bool  sLast;
    if (tid < NCOL) sh[tid] = 0.0f;
    __syncthreads();
    if (lane < 4) {
#pragma unroll
        for (int ss = 0; ss < 4; ss++) {
            const int bin = q + 4 * ss;
            if (bin < NBINS) {
                atomicAdd(&sh[bin],             cnt[ss]);
                atomicAdd(&sh[NBINS + bin],     csum[ss]);
                atomicAdd(&sh[2 * NBINS + bin], asum[ss]);
            }
        }
    }
    __syncthreads();
    if (tid < NCOL)
        atomicAdd(&g_red[tid * PAD], (double)sh[tid]);

    // ---- last block finalizes ----
    __threadfence();
    if (tid == 0)
        sLast = (atomicAdd(&g_ticket, 1u) == (unsigned)(gridDim.x - 1));
    __syncthreads();
    if (sLast)
        finalize_ece(out, nAll, tid);
}

// ---------------------------------------------------------------------------
// Generic fallback (any C): warp per row, fused finalization.
// ---------------------------------------------------------------------------
__global__ __launch_bounds__(TPB)
void ece_pass1_generic(const float* __restrict__ logits,
                       const int*   __restrict__ labels,
                       int N, int C, float* __restrict__ out, double nAll)
{
    const int tid  = threadIdx.x;
    const int lane = tid & 31;
    const int warpId = blockIdx.x * WPB + (tid >> 5);
    const int nWarps = NBLK * WPB;
    const float L2E = 1.4426950408889634f;

    __shared__ float sh[NCOL];
    __shared__ bool  sLast;
    if (tid < NCOL) sh[tid] = 0.0f;
    __syncthreads();

    for (int row = warpId; row < N; row += nWarps) {
        const float* rp = logits + (size_t)row * C;
        float m = -3.4e38f;
        int am = 0x7fffffff;
        for (int j = lane; j < C; j += 32) {
            float v = rp[j];
            if (v > m) { m = v; am = j; }
        }
#pragma unroll
        for (int d = 1; d < 32; d <<= 1) {
            float om = __shfl_xor_sync(0xffffffffu, m, d);
            int   oa = __shfl_xor_sync(0xffffffffu, am, d);
            if (om > m || (om == m && oa < am)) { m = om; am = oa; }
        }
        const float mb = m * L2E;
        float s = 0.f;
        for (int j = lane; j < C; j += 32)
            s += ex2f(fmaf(rp[j], L2E, -mb));
#pragma unroll
        for (int d = 1; d < 32; d <<= 1)
            s += __shfl_xor_sync(0xffffffffu, s, d);

        if (lane == 0) {
            const float conf = 1.0f / s;
            const float accv = (am == labels[row]) ? 1.0f : 0.0f;
            int bin = (int)(conf * 15.0f);
            bin = min(bin, NBINS - 1);
            atomicAdd(&sh[bin],             1.0f);
            atomicAdd(&sh[NBINS + bin],     conf);
            atomicAdd(&sh[2 * NBINS + bin], accv);
        }
    }
    __syncthreads();
    if (tid < NCOL)
        atomicAdd(&g_red[tid * PAD], (double)sh[tid]);

    __threadfence();
    if (tid == 0)
        sLast = (atomicAdd(&g_ticket, 1u) == (unsigned)(gridDim.x - 1));
    __syncthreads();
    if (sLast)
        finalize_ece(out, nAll, tid);
}

extern "C" void kernel_launch(void* const* d_in, const int* in_sizes, int n_in,
                              void* d_out, int out_size)
{
    const float* logits = (const float*)d_in[0];
    const int*   labels = (const int*)d_in[1];
    const long long total = (long long)in_sizes[0];
    const int N = in_sizes[1];
    const int C = (int)(total / N);

    if (C == 100)
        ece_pass1_c100<<<NBLK, TPB>>>(logits, labels, N, (float*)d_out, (double)N);
    else
        ece_pass1_generic<<<NBLK, TPB>>>(logits, labels, N, C, (float*)d_out, (double)N);
}